// round 15
// baseline (speedup 1.0000x reference)
#include <cuda_runtime.h>

// Tensors [B=64, S=100, K=4, H=32, W=32] fp32; only channel k=3 is read:
// contiguous 1024-float run at s*4096 + 3072 for each of 6400 (b,s) slices.
// result = mean(|convdata[:,:,3] - output[:,:,3]|) over 6400*1024 elements.
//
// R8 experiment: scalar LDG.32 loads (one 128B line per warp-LDG, 1.0 cyc/wf)
// instead of LDG.128 (4 lines, 2.07 cyc/wf within-LDG replays) to relieve the
// L1tex wavefront pipe on the warm-L2 path. Geometry = champion (400x16).

static constexpr int NUM_SLICES   = 64 * 100;    // 6400
static constexpr int SLICE_STRIDE = 4 * 32 * 32; // 4096 floats per (b,s)
static constexpr int CH3_OFFSET   = 3 * 32 * 32; // 3072
static constexpr int SLICE_ELEMS  = 32 * 32;     // 1024 floats

static constexpr int THREADS = 256;
static constexpr int BLOCKS  = 400;              // single balanced wave
static constexpr int SLICES_PER_BLOCK = NUM_SLICES / BLOCKS;  // 16
static constexpr int CHUNK   = 2;                // slices per pipeline stage
static constexpr int NCHUNKS = SLICES_PER_BLOCK / CHUNK;      // 8
static constexpr int Q = SLICE_ELEMS / THREADS;  // 4 floats per thread per slice

// Cross-block fan-in scratch (device globals: allocation-free).
// Invariant: zero at every launch; last finishing block re-zeros after publishing.
__device__ float        g_accum = 0.0f;
__device__ unsigned int g_count = 0u;

__global__ __launch_bounds__(THREADS, 4) void abs_diff_mean_kernel(
    const float* __restrict__ a,   // "output" tensor
    const float* __restrict__ b,   // "convdata" tensor
    float* __restrict__ res)
{
    const int tid = threadIdx.x;

    // This block's 16 contiguous slices. Thread t loads floats t, t+256,
    // t+512, t+768 of each slice: every warp-LDG covers exactly one 128B line.
    const size_t base = (size_t)blockIdx.x * SLICES_PER_BLOCK * SLICE_STRIDE
                      + CH3_OFFSET + (size_t)tid;
    const float* pa = a + base;
    const float* pb = b + base;

    float ca[CHUNK][Q], cb[CHUNK][Q];   // current chunk (being consumed)
    float na[CHUNK][Q], nb[CHUNK][Q];   // next chunk (in flight)

    // Prologue: chunk 0 in flight (16 independent LDG.32).
    #pragma unroll
    for (int i = 0; i < CHUNK; i++)
        #pragma unroll
        for (int j = 0; j < Q; j++) {
            ca[i][j] = pa[i * SLICE_STRIDE + j * THREADS];
            cb[i][j] = pb[i * SLICE_STRIDE + j * THREADS];
        }

    float acc0 = 0.0f, acc1 = 0.0f, acc2 = 0.0f, acc3 = 0.0f;

    // Steady state: prefetch chunk c while consuming chunk c-1.
    #pragma unroll
    for (int c = 1; c < NCHUNKS; c++) {
        #pragma unroll
        for (int i = 0; i < CHUNK; i++) {
            const size_t s = (size_t)(c * CHUNK + i) * SLICE_STRIDE;
            #pragma unroll
            for (int j = 0; j < Q; j++) {
                na[i][j] = pa[s + j * THREADS];
                nb[i][j] = pb[s + j * THREADS];
            }
        }
        #pragma unroll
        for (int i = 0; i < CHUNK; i++) {
            acc0 += fabsf(cb[i][0] - ca[i][0]);
            acc1 += fabsf(cb[i][1] - ca[i][1]);
            acc2 += fabsf(cb[i][2] - ca[i][2]);
            acc3 += fabsf(cb[i][3] - ca[i][3]);
            #pragma unroll
            for (int j = 0; j < Q; j++) { ca[i][j] = na[i][j]; cb[i][j] = nb[i][j]; }
        }
    }

    // Epilogue: consume final chunk.
    #pragma unroll
    for (int i = 0; i < CHUNK; i++) {
        acc0 += fabsf(cb[i][0] - ca[i][0]);
        acc1 += fabsf(cb[i][1] - ca[i][1]);
        acc2 += fabsf(cb[i][2] - ca[i][2]);
        acc3 += fabsf(cb[i][3] - ca[i][3]);
    }

    float acc = (acc0 + acc1) + (acc2 + acc3);

    // Warp reduce
    #pragma unroll
    for (int off = 16; off > 0; off >>= 1)
        acc += __shfl_xor_sync(0xFFFFFFFFu, acc, off);

    __shared__ float warp_sums[THREADS / 32];
    if ((tid & 31) == 0) warp_sums[tid >> 5] = acc;
    __syncthreads();

    if (tid == 0) {
        float v = 0.0f;
        #pragma unroll
        for (int w = 0; w < THREADS / 32; w++) v += warp_sums[w];

        atomicAdd(&g_accum, v);
        __threadfence();
        unsigned int done = atomicAdd(&g_count, 1u);
        if (done == (unsigned)(gridDim.x - 1)) {
            float total = atomicExch(&g_accum, 0.0f);   // read + reset scratch
            const float inv_total = 1.0f / ((float)NUM_SLICES * (float)SLICE_ELEMS);
            res[0] = total * inv_total;
            g_count = 0u;                               // reset for next replay
        }
    }
}

extern "C" void kernel_launch(void* const* d_in, const int* in_sizes, int n_in,
                              void* d_out, int out_size) {
    const float* out_t  = (const float*)d_in[0];  // "output"
    const float* conv_t = (const float*)d_in[1];  // "convdata"
    float* res = (float*)d_out;

    abs_diff_mean_kernel<<<BLOCKS, THREADS>>>(out_t, conv_t, res);
}

// round 16
// speedup vs baseline: 1.0388x; 1.0388x over previous
#include <cuda_runtime.h>

// Tensors [B=64, S=100, K=4, H=32, W=32] fp32; only channel k=3 is read:
// contiguous 1024-float run at s*4096 + 3072 for each of 6400 (b,s) slices.
// result = mean(|convdata[:,:,3] - output[:,:,3]|) over 6400*1024 elements.
//
// R9: persistent-style 1 CTA/SM (grid=148). Occupancy is grid-limited, so a
// deep CHUNK=4 pipeline (16 LDG.128 in flight, ~128 regs) is free — the
// R6 failure mode (regs halving resident CTAs) cannot occur here.

static constexpr int NUM_SLICES   = 64 * 100;    // 6400
static constexpr int SLICE_STRIDE = 4 * 32 * 32; // 4096 floats per (b,s)
static constexpr int CH3_OFFSET   = 3 * 32 * 32; // 3072
static constexpr int SLICE_ELEMS  = 32 * 32;     // 1024 floats

static constexpr int THREADS = 256;
static constexpr int BLOCKS  = 148;              // exactly 1 CTA per SM
static constexpr int BASE_SLICES = NUM_SLICES / BLOCKS;                       // 43
static constexpr int FAT_BLOCKS  = NUM_SLICES - BLOCKS * BASE_SLICES;         // 36 blocks get 44
static constexpr int CHUNK = 4;                  // slices per stage (8 LDG.128/stage)

// Cross-block fan-in scratch (device globals: allocation-free).
// Invariant: zero at every launch; last finishing block re-zeros after publishing.
__device__ float        g_accum = 0.0f;
__device__ unsigned int g_count = 0u;

__global__ __launch_bounds__(THREADS, 1) void abs_diff_mean_kernel(
    const float* __restrict__ a,   // "output" tensor
    const float* __restrict__ b,   // "convdata" tensor
    float* __restrict__ res)
{
    const int tid = threadIdx.x;
    const int bid = blockIdx.x;

    // Uneven contiguous partition: blocks [0,36) own 44 slices, the rest 43.
    const int extra = (bid < FAT_BLOCKS) ? bid : FAT_BLOCKS;
    const int start = bid * BASE_SLICES + extra;
    const int count = BASE_SLICES + ((bid < FAT_BLOCKS) ? 1 : 0);   // 43 or 44

    const size_t base = (size_t)start * SLICE_STRIDE + CH3_OFFSET + (size_t)tid * 4;
    const float* pa = a + base;
    const float* pb = b + base;

    const int nfull = count / CHUNK;        // 10 or 11 full stages
    const int rem   = count - nfull * CHUNK; // 3 or 0 tail slices

    float4 ca[CHUNK], cb[CHUNK];   // current stage (being consumed)
    float4 na[CHUNK], nb[CHUNK];   // next stage (in flight)

    // Prologue: stage 0 in flight (8 independent LDG.128).
    #pragma unroll
    for (int i = 0; i < CHUNK; i++) {
        ca[i] = *reinterpret_cast<const float4*>(pa + (size_t)i * SLICE_STRIDE);
        cb[i] = *reinterpret_cast<const float4*>(pb + (size_t)i * SLICE_STRIDE);
    }

    float acc0 = 0.0f, acc1 = 0.0f, acc2 = 0.0f, acc3 = 0.0f;

    // Steady state: prefetch stage c while consuming stage c-1 (16 loads in flight).
    for (int c = 1; c < nfull; c++) {
        const size_t s = (size_t)c * CHUNK * SLICE_STRIDE;
        #pragma unroll
        for (int i = 0; i < CHUNK; i++) {
            na[i] = *reinterpret_cast<const float4*>(pa + s + (size_t)i * SLICE_STRIDE);
            nb[i] = *reinterpret_cast<const float4*>(pb + s + (size_t)i * SLICE_STRIDE);
        }
        #pragma unroll
        for (int i = 0; i < CHUNK; i++) {
            acc0 += fabsf(cb[i].x - ca[i].x);
            acc1 += fabsf(cb[i].y - ca[i].y);
            acc2 += fabsf(cb[i].z - ca[i].z);
            acc3 += fabsf(cb[i].w - ca[i].w);
            ca[i] = na[i];
            cb[i] = nb[i];
        }
    }

    // Tail prefetch (up to 3 slices) overlaps with final full stage consumption.
    #pragma unroll
    for (int i = 0; i < CHUNK - 1; i++) {
        if (i < rem) {
            const size_t s = (size_t)(nfull * CHUNK + i) * SLICE_STRIDE;
            na[i] = *reinterpret_cast<const float4*>(pa + s);
            nb[i] = *reinterpret_cast<const float4*>(pb + s);
        }
    }

    // Consume final full stage.
    #pragma unroll
    for (int i = 0; i < CHUNK; i++) {
        acc0 += fabsf(cb[i].x - ca[i].x);
        acc1 += fabsf(cb[i].y - ca[i].y);
        acc2 += fabsf(cb[i].z - ca[i].z);
        acc3 += fabsf(cb[i].w - ca[i].w);
    }

    // Consume tail slices.
    #pragma unroll
    for (int i = 0; i < CHUNK - 1; i++) {
        if (i < rem) {
            acc0 += fabsf(nb[i].x - na[i].x);
            acc1 += fabsf(nb[i].y - na[i].y);
            acc2 += fabsf(nb[i].z - na[i].z);
            acc3 += fabsf(nb[i].w - na[i].w);
        }
    }

    float acc = (acc0 + acc1) + (acc2 + acc3);

    // Warp reduce
    #pragma unroll
    for (int off = 16; off > 0; off >>= 1)
        acc += __shfl_xor_sync(0xFFFFFFFFu, acc, off);

    __shared__ float warp_sums[THREADS / 32];
    if ((tid & 31) == 0) warp_sums[tid >> 5] = acc;
    __syncthreads();

    if (tid == 0) {
        float v = 0.0f;
        #pragma unroll
        for (int w = 0; w < THREADS / 32; w++) v += warp_sums[w];

        atomicAdd(&g_accum, v);
        __threadfence();
        unsigned int done = atomicAdd(&g_count, 1u);
        if (done == (unsigned)(gridDim.x - 1)) {
            float total = atomicExch(&g_accum, 0.0f);   // read + reset scratch
            const float inv_total = 1.0f / ((float)NUM_SLICES * (float)SLICE_ELEMS);
            res[0] = total * inv_total;
            g_count = 0u;                               // reset for next replay
        }
    }
}

extern "C" void kernel_launch(void* const* d_in, const int* in_sizes, int n_in,
                              void* d_out, int out_size) {
    const float* out_t  = (const float*)d_in[0];  // "output"
    const float* conv_t = (const float*)d_in[1];  // "convdata"
    float* res = (float*)d_out;

    abs_diff_mean_kernel<<<BLOCKS, THREADS>>>(out_t, conv_t, res);
}

// round 17
// speedup vs baseline: 1.0708x; 1.0308x over previous
#include <cuda_runtime.h>

// Tensors [B=64, S=100, K=4, H=32, W=32] fp32; only channel k=3 is read:
// contiguous 1024-float run at s*4096 + 3072 for each of 6400 (b,s) slices.
// result = mean(|convdata[:,:,3] - output[:,:,3]|) over 6400*1024 elements.
//
// R10: champion geometry (400x16, single balanced wave) with CHUNK=3.
// grid=400 needs only ceil(400/148)=3 resident CTAs/SM, so launch_bounds(256,3)
// (reg cap 85) keeps the champion's schedule while deepening the pipeline to
// 12 LDG.128 in flight per thread (vs 8). Isolates depth from occupancy.

static constexpr int NUM_SLICES   = 64 * 100;    // 6400
static constexpr int SLICE_STRIDE = 4 * 32 * 32; // 4096 floats per (b,s)
static constexpr int CH3_OFFSET   = 3 * 32 * 32; // 3072
static constexpr int SLICE_ELEMS  = 32 * 32;     // 1024 floats

static constexpr int THREADS = 256;              // one float4 per thread per slice
static constexpr int BLOCKS  = 400;              // single balanced wave (<=444 slots @3/SM)
static constexpr int SLICES_PER_BLOCK = NUM_SLICES / BLOCKS;  // 16
static constexpr int CHUNK   = 3;                // slices per stage (6 LDG.128/stage)
static constexpr int NFULL   = SLICES_PER_BLOCK / CHUNK;      // 5 full stages
static constexpr int REM     = SLICES_PER_BLOCK - NFULL * CHUNK; // 1 tail slice

// Cross-block fan-in scratch (device globals: allocation-free).
// Invariant: zero at every launch; last finishing block re-zeros after publishing.
__device__ float        g_accum = 0.0f;
__device__ unsigned int g_count = 0u;

__global__ __launch_bounds__(THREADS, 3) void abs_diff_mean_kernel(
    const float* __restrict__ a,   // "output" tensor
    const float* __restrict__ b,   // "convdata" tensor
    float* __restrict__ res)
{
    const int tid = threadIdx.x;

    // This block's 16 contiguous slices; thread t owns one float4 per slice.
    const size_t base = (size_t)blockIdx.x * SLICES_PER_BLOCK * SLICE_STRIDE
                      + CH3_OFFSET + (size_t)tid * 4;
    const float* pa = a + base;
    const float* pb = b + base;

    float4 ca[CHUNK], cb[CHUNK];   // current stage (being consumed)
    float4 na[CHUNK], nb[CHUNK];   // next stage (in flight)

    // Prologue: stage 0 in flight (6 independent LDG.128).
    #pragma unroll
    for (int i = 0; i < CHUNK; i++) {
        ca[i] = *reinterpret_cast<const float4*>(pa + (size_t)i * SLICE_STRIDE);
        cb[i] = *reinterpret_cast<const float4*>(pb + (size_t)i * SLICE_STRIDE);
    }

    float acc0 = 0.0f, acc1 = 0.0f, acc2 = 0.0f, acc3 = 0.0f;

    // Steady state: prefetch stage c while consuming stage c-1 (12 loads in flight).
    #pragma unroll
    for (int c = 1; c < NFULL; c++) {
        const size_t s = (size_t)c * CHUNK * SLICE_STRIDE;
        #pragma unroll
        for (int i = 0; i < CHUNK; i++) {
            na[i] = *reinterpret_cast<const float4*>(pa + s + (size_t)i * SLICE_STRIDE);
            nb[i] = *reinterpret_cast<const float4*>(pb + s + (size_t)i * SLICE_STRIDE);
        }
        #pragma unroll
        for (int i = 0; i < CHUNK; i++) {
            acc0 += fabsf(cb[i].x - ca[i].x);
            acc1 += fabsf(cb[i].y - ca[i].y);
            acc2 += fabsf(cb[i].z - ca[i].z);
            acc3 += fabsf(cb[i].w - ca[i].w);
            ca[i] = na[i];
            cb[i] = nb[i];
        }
    }

    // Tail slice prefetch (overlaps final full stage consumption).
    {
        const size_t s = (size_t)(NFULL * CHUNK) * SLICE_STRIDE;
        na[0] = *reinterpret_cast<const float4*>(pa + s);
        nb[0] = *reinterpret_cast<const float4*>(pb + s);
    }

    // Consume final full stage.
    #pragma unroll
    for (int i = 0; i < CHUNK; i++) {
        acc0 += fabsf(cb[i].x - ca[i].x);
        acc1 += fabsf(cb[i].y - ca[i].y);
        acc2 += fabsf(cb[i].z - ca[i].z);
        acc3 += fabsf(cb[i].w - ca[i].w);
    }

    // Consume tail slice (REM == 1).
    static_assert(REM == 1, "tail handling assumes exactly one leftover slice");
    acc0 += fabsf(nb[0].x - na[0].x);
    acc1 += fabsf(nb[0].y - na[0].y);
    acc2 += fabsf(nb[0].z - na[0].z);
    acc3 += fabsf(nb[0].w - na[0].w);

    float acc = (acc0 + acc1) + (acc2 + acc3);

    // Warp reduce
    #pragma unroll
    for (int off = 16; off > 0; off >>= 1)
        acc += __shfl_xor_sync(0xFFFFFFFFu, acc, off);

    __shared__ float warp_sums[THREADS / 32];
    if ((tid & 31) == 0) warp_sums[tid >> 5] = acc;
    __syncthreads();

    if (tid == 0) {
        float v = 0.0f;
        #pragma unroll
        for (int w = 0; w < THREADS / 32; w++) v += warp_sums[w];

        atomicAdd(&g_accum, v);
        __threadfence();
        unsigned int done = atomicAdd(&g_count, 1u);
        if (done == (unsigned)(gridDim.x - 1)) {
            float total = atomicExch(&g_accum, 0.0f);   // read + reset scratch
            const float inv_total = 1.0f / ((float)NUM_SLICES * (float)SLICE_ELEMS);
            res[0] = total * inv_total;
            g_count = 0u;                               // reset for next replay
        }
    }
}

extern "C" void kernel_launch(void* const* d_in, const int* in_sizes, int n_in,
                              void* d_out, int out_size) {
    const float* out_t  = (const float*)d_in[0];  // "output"
    const float* conv_t = (const float*)d_in[1];  // "convdata"
    float* res = (float*)d_out;

    abs_diff_mean_kernel<<<BLOCKS, THREADS>>>(out_t, conv_t, res);
}